// round 12
// baseline (speedup 1.0000x reference)
#include <cuda_runtime.h>
#include <cuda_fp16.h>
#include <math.h>
#include <stdint.h>

// Shapes (fixed)
#define Bn   16
#define Hh   64
#define Ww   64
#define C1   16
#define C2   16
#define HIDc 128
#define OC4  272          // C2*(C2+1)
#define NPIX (Bn*Hh*Ww)   // 65536

// ---------------------------------------------------------------------------
__device__ __forceinline__ uint32_t smem_u32(const void* p) {
    uint32_t a;
    asm("{ .reg .u64 t; cvta.to.shared.u64 t, %1; cvt.u32.u64 %0, t; }" : "=r"(a) : "l"(p));
    return a;
}

__device__ __forceinline__ void ldsm_x4(uint32_t (&r)[4], uint32_t addr) {
    asm volatile("ldmatrix.sync.aligned.m8n8.x4.shared.b16 {%0,%1,%2,%3}, [%4];"
        : "=r"(r[0]), "=r"(r[1]), "=r"(r[2]), "=r"(r[3]) : "r"(addr));
}

__device__ __forceinline__ void mma16816(float (&d)[4], const uint32_t (&a)[4],
                                         uint32_t b0, uint32_t b1) {
    asm volatile("mma.sync.aligned.m16n8k16.row.col.f32.f16.f16.f32 "
        "{%0,%1,%2,%3}, {%4,%5,%6,%7}, {%8,%9}, {%0,%1,%2,%3};"
        : "+f"(d[0]), "+f"(d[1]), "+f"(d[2]), "+f"(d[3])
        : "r"(a[0]), "r"(a[1]), "r"(a[2]), "r"(a[3]), "r"(b0), "r"(b1));
}

__device__ __forceinline__ void cp16(uint32_t dst, const void* src, bool pred) {
    asm volatile("cp.async.cg.shared.global [%0], [%1], 16, %2;"
        :: "r"(dst), "l"(src), "r"(pred ? 16u : 0u) : "memory");
}
#define CP_COMMIT() asm volatile("cp.async.commit_group;" ::: "memory")
#define CP_WAIT0()  asm volatile("cp.async.wait_group 0;" ::: "memory")
#define CP_WAIT1()  asm volatile("cp.async.wait_group 1;" ::: "memory")

__device__ __forceinline__ float eluf(float t) { return t > 0.0f ? t : expm1f(t); }

__device__ __forceinline__ float tanh_fast(float x) {
    float y;
    asm("tanh.approx.f32 %0, %1;" : "=f"(y) : "f"(x));
    return y;
}

// ---------------- scratch (device globals) ----------------
__device__ __align__(16) __half g_x1h[NPIX * C1];
__device__ __align__(16) float  g_x2t[NPIX * C2];
__device__ __align__(16) __half g_a0[NPIX * HIDc];
__device__ __align__(16) __half g_a1[NPIX * HIDc];
__device__ __align__(16) float  g_o [(size_t)NPIX * OC4];
// pre-tiled weights: [tile64][tap][64 oc][ICA] fp16
__device__ __align__(16) __half g_wb0[2 * 9 * 64 * 16];
__device__ __align__(16) __half g_wb1[2 * 9 * 64 * 128];
__device__ __align__(16) __half g_wb2[2 * 9 * 64 * 128];
__device__ __align__(16) __half g_wb3[5 * 9 * 64 * 128];

// ---------------------------------------------------------------------------
// prep: NCHW -> NHWC split (x1 as fp16, x2 fp32), passthrough, zero logdet
// ---------------------------------------------------------------------------
__global__ void prep_kernel(const float* __restrict__ x, float* __restrict__ out)
{
    int idx = blockIdx.x * blockDim.x + threadIdx.x;
    if (idx < Bn) out[(size_t)Bn * 32 * Hh * Ww + idx] = 0.0f;
    if (idx >= Bn * 32 * Hh * Ww) return;
    int b = idx >> 17;
    int c = (idx >> 12) & 31;
    int p = idx & 4095;
    float v = x[idx];
    int pix = (b << 12) + p;
    if (c < C1) {
        out[idx] = v;
        g_x1h[pix * C1 + c] = __float2half_rn(v);
    } else {
        g_x2t[pix * C2 + (c - C1)] = v;
    }
}

// ---------------------------------------------------------------------------
// wprep_all: tile ALL four weight tensors into fp16 64-oc tiles in one launch
// ---------------------------------------------------------------------------
#define WN0 (2 * 9 * 64 * 16)
#define WN1 (2 * 9 * 64 * 128)
#define WN3 (5 * 9 * 64 * 128)
__global__ void wprep_all(const float* __restrict__ w0, const float* __restrict__ w1,
                          const float* __restrict__ w2, const float* __restrict__ w3,
                          __half* __restrict__ d0, __half* __restrict__ d1,
                          __half* __restrict__ d2, __half* __restrict__ d3)
{
    int gi = blockIdx.x * blockDim.x + threadIdx.x;
    const float* w; __half* d; int OC, ICA, li;
    if (gi < WN0)                 { li = gi;                 w = w0; d = d0; OC = HIDc; ICA = C1;   }
    else if (gi < WN0 + WN1)      { li = gi - WN0;           w = w1; d = d1; OC = HIDc; ICA = HIDc; }
    else if (gi < WN0 + 2 * WN1)  { li = gi - WN0 - WN1;     w = w2; d = d2; OC = HIDc; ICA = HIDc; }
    else if (gi < WN0 + 2 * WN1 + WN3) { li = gi - WN0 - 2 * WN1; w = w3; d = d3; OC = OC4; ICA = HIDc; }
    else return;
    int k   = li % ICA;
    int row = (li / ICA) & 63;
    int tt  = li / (ICA * 64);
    int tap  = tt % 9;
    int tile = tt / 9;
    int oc = tile * 64 + row;
    float v = (oc < OC) ? w[((size_t)oc * ICA + k) * 9 + tap] : 0.0f;
    d[li] = __float2half_rn(v);
}

// ---------------------------------------------------------------------------
// B-tile stager: one tap (64 rows x ICA) into padded SMEM via cp.async
// ---------------------------------------------------------------------------
template<int ICA>
__device__ __forceinline__ void stage_B(uint32_t dst, const __half* __restrict__ wsrc, int tid)
{
    constexpr int VPA = ICA / 8;
    constexpr int PB  = (ICA + 8) * 2;
    const char* bsrc = (const char*)wsrc;
    for (int vi = tid; vi < 64 * VPA; vi += 256) {
        int row = vi / VPA, kv = vi % VPA;
        cp16(dst + row * PB + kv * 16, bsrc + vi * 16, true);
    }
}

// ---------------------------------------------------------------------------
// Implicit 3x3 conv via mma.sync (pure fp16); A halo resident.
// CTA = 128 px (2 image rows) x 64 oc, 8 warps (4M x 2N), warp = 32px x 32oc.
// B TRIPLE-buffered: one __syncthreads per tap (stage target = last-read-2-taps-ago).
// ---------------------------------------------------------------------------
template<int ICA>
__global__ __launch_bounds__(256)
void conv_mma_kernel(const __half* __restrict__ in,
                     const __half* __restrict__ wb,
                     const float* __restrict__ bias,
                     __half* __restrict__ out_h,
                     float* __restrict__ out_f32,
                     int OC_total)
{
    constexpr int PITCH = ICA + 8;
    constexpr int PB    = PITCH * 2;
    constexpr int AROWS = 4 * 66;
    constexpr int ATILE = AROWS * PB;
    constexpr int BTILE = 64 * PB;
    constexpr int VPA   = ICA / 8;
    constexpr int KC    = ICA / 16;

    extern __shared__ char smem[];
    const uint32_t sA = smem_u32(smem);
    const uint32_t sB = sA + ATILE;         // [3 bufs]

    const int tid  = threadIdx.x;
    const int lane = tid & 31;
    const int warp = tid >> 5;
    const int warpN = warp & 1;
    const int warpM = warp >> 1;

    const int pixbase = blockIdx.x * 128;
    const int b  = pixbase >> 12;
    const int y0 = (pixbase & 4095) >> 6;
    const int ocb = blockIdx.y;
    const bool active = (ocb * 64 + warpN * 32) < OC_total;
    const size_t wbase = (size_t)ocb * 9 * (64 * ICA);

    float acc[2][4][4];
    #pragma unroll
    for (int mt = 0; mt < 2; mt++)
        #pragma unroll
        for (int nt = 0; nt < 4; nt++)
            #pragma unroll
            for (int q = 0; q < 4; q++) acc[mt][nt][q] = 0.0f;

    // ---- prologue: A halo + B[0] (group0), B[1] (group1) ----
    for (int vi = tid; vi < AROWS * VPA; vi += 256) {
        int row = vi / VPA;
        int kv  = vi % VPA;
        int yy  = y0 + row / 66 - 1;
        int xx  = (row % 66) - 1;
        bool ok = (yy >= 0 && yy < Hh && xx >= 0 && xx < Ww);
        size_t src = ok ? (((size_t)((b << 12) + (yy << 6) + xx)) * ICA + kv * 8) : 0;
        cp16(sA + row * PB + kv * 16, in + src, ok);
    }
    stage_B<ICA>(sB, wb + wbase, tid);
    CP_COMMIT();
    stage_B<ICA>(sB + BTILE, wb + wbase + 64 * ICA, tid);
    CP_COMMIT();
    CP_WAIT1();            // A + B[0] resident (B[1] may still fly)
    __syncthreads();

    // per-lane ldmatrix base offsets
    const uint32_t a_base = (uint32_t)(((warpM >> 1) + 1) * 66
                          + (warpM & 1) * 32 + (lane & 15) + 1) * PB
                          + (uint32_t)(lane & 16);
    const uint32_t b_base = (uint32_t)(warpN * 32 + (lane & 7) + ((lane & 16) >> 1)) * PB
                          + (uint32_t)((lane & 8) << 1);

    #pragma unroll
    for (int tap = 0; tap < 9; tap++) {
        const uint32_t buf = sB + (uint32_t)(tap % 3) * BTILE;

        // stage B[tap+2] into the buffer read at tap-1 (all warps left it
        // before the barrier that ended iteration tap-1) — no extra barrier.
        if (tap + 2 <= 8) {
            stage_B<ICA>(sB + (uint32_t)((tap + 2) % 3) * BTILE,
                         wb + wbase + (size_t)(tap + 2) * 64 * ICA, tid);
            CP_COMMIT();
        }

        if (active) {
            const int dy = tap / 3 - 1, dx = tap % 3 - 1;
            const uint32_t tapoff = (uint32_t)((dy * 66 + dx) * PB);
            #pragma unroll
            for (int kc = 0; kc < KC; kc++) {
                const uint32_t k0b = kc * 32;
                uint32_t A[2][4], B[2][4];
                #pragma unroll
                for (int mt = 0; mt < 2; mt++)
                    ldsm_x4(A[mt], sA + a_base + tapoff + k0b + (uint32_t)(mt * 16) * PB);
                #pragma unroll
                for (int p = 0; p < 2; p++)
                    ldsm_x4(B[p], buf + b_base + k0b + (uint32_t)(p * 16) * PB);
                #pragma unroll
                for (int mt = 0; mt < 2; mt++)
                    #pragma unroll
                    for (int nt = 0; nt < 4; nt++) {
                        const int pr = nt >> 1, rr = (nt & 1) * 2;
                        mma16816(acc[mt][nt], A[mt], B[pr][rr], B[pr][rr + 1]);
                    }
            }
        }

        // wait so that B[tap+1] is complete (at most B[tap+2] still pending),
        // then one barrier: everyone done reading buf[tap], B[tap+1] visible.
        if (tap + 2 <= 8) { CP_WAIT1(); } else { CP_WAIT0(); }
        __syncthreads();
    }

    // --- epilogue ---
    if (!active) return;
    #pragma unroll
    for (int mt = 0; mt < 2; mt++) {
        #pragma unroll
        for (int nt = 0; nt < 4; nt++) {
            const int cl = warpN * 32 + nt * 8 + (lane & 3) * 2;
            const int oc = ocb * 64 + cl;
            if (oc >= OC_total) continue;
            const float b0 = bias[oc], b1 = bias[oc + 1];
            const int r0 = pixbase + (warpM >> 1) * 64 + (warpM & 1) * 32
                         + mt * 16 + (lane >> 2);
            #pragma unroll
            for (int h = 0; h < 2; h++) {
                const int pix = r0 + h * 8;
                float v0 = acc[mt][nt][2 * h]     + b0;
                float v1 = acc[mt][nt][2 * h + 1] + b1;
                if (out_f32) {
                    *(float2*)(out_f32 + (size_t)pix * OC4 + oc) = make_float2(v0, v1);
                } else {
                    v0 = eluf(v0);
                    v1 = eluf(v1);
                    __half h0 = __float2half_rn(v0);
                    __half h1 = __float2half_rn(v1);
                    uint32_t hw = (uint32_t)__half_as_ushort(h0) | ((uint32_t)__half_as_ushort(h1) << 16);
                    *(uint32_t*)(out_h + (size_t)pix * 128 + oc) = hw;
                }
            }
        }
    }
}

// ---------------------------------------------------------------------------
// expm kernel: y2 = sum_{k=0..12} A^k x2 / k!  (terms 13-18 < 2e-10, ||A||<=1)
// A via tanh.approx; trace via accurate tanhf. One syncwarp/iter (double buf).
// ---------------------------------------------------------------------------
__global__ __launch_bounds__(256)
void expm_kernel(const float* __restrict__ o,
                 const float* __restrict__ scale, const float* __restrict__ shift_p,
                 const float* __restrict__ rescale, const float* __restrict__ reshift,
                 float* __restrict__ out)
{
    __shared__ float sT[16][2][20];
    __shared__ float sY[16][17];
    __shared__ float sTr[8];

    const int tid  = threadIdx.x;
    const int lane = tid & 31;
    const int warp = tid >> 5;
    const int half = lane >> 4;
    const int r    = lane & 15;
    const int pixB = warp * 2 + half;

    const int pix_base = blockIdx.x * 16;
    const int b  = pix_base >> 12;
    const int p  = pix_base & 4095;
    const int y  = p >> 6;
    const int x0 = p & 63;
    const int pix = pix_base + pixB;

    const float sc = scale[0], sp = shift_p[0], rs = rescale[0], rf = reshift[0];
    const float* op = o + (size_t)pix * OC4;

    float arow[16];
    #pragma unroll
    for (int j = 0; j < 16; j++) {
        float v = op[(j + 1) * 16 + r];
        arow[j] = rs * tanh_fast(sc * v + sp) + rf;
    }
    // accurate trace (same math path as validated rounds)
    float tr = rs * tanhf(sc * op[(r + 1) * 16 + r] + sp) + rf;

    const float x2v = g_x2t[(size_t)pix * 16 + r];
    sT[pixB][0][r] = x2v;
    float yacc = x2v;
    __syncwarp();

    #pragma unroll
    for (int k = 1; k <= 12; k++) {
        const int prev = (k - 1) & 1, cur = k & 1;
        float s = 0.0f;
        #pragma unroll
        for (int j = 0; j < 16; j++) s = fmaf(arow[j], sT[pixB][prev][j], s);
        s *= (1.0f / (float)k);
        sT[pixB][cur][r] = s;
        yacc += s;
        __syncwarp();
    }

    sY[pixB][r] = yacc + op[r];

    #pragma unroll
    for (int off = 16; off > 0; off >>= 1) tr += __shfl_down_sync(0xffffffffu, tr, off);
    if (lane == 0) sTr[warp] = tr;
    __syncthreads();
    if (tid == 0) {
        float s = 0.0f;
        #pragma unroll
        for (int w2 = 0; w2 < 8; w2++) s += sTr[w2];
        atomicAdd(out + (size_t)Bn * 32 * Hh * Ww + b, s);
    }

    const int c  = tid >> 4;
    const int p2 = tid & 15;
    out[((size_t)(b * 32 + 16 + c)) * (Hh * Ww) + y * Ww + x0 + p2] = sY[p2][c];
}

// ---------------------------------------------------------------------------
extern "C" void kernel_launch(void* const* d_in, const int* in_sizes, int n_in,
                              void* d_out, int out_size)
{
    const float* x       = (const float*)d_in[0];
    const float* scale   = (const float*)d_in[1];
    const float* shift_p = (const float*)d_in[2];
    const float* rescale = (const float*)d_in[3];
    const float* reshift = (const float*)d_in[4];
    const float* w0 = (const float*)d_in[5];
    const float* b0 = (const float*)d_in[6];
    const float* w1 = (const float*)d_in[7];
    const float* b1 = (const float*)d_in[8];
    const float* w2 = (const float*)d_in[9];
    const float* b2 = (const float*)d_in[10];
    const float* w3 = (const float*)d_in[11];
    const float* b3 = (const float*)d_in[12];
    float* out = (float*)d_out;

    __half *x1h, *a0, *a1, *wb0, *wb1, *wb2, *wb3;
    float *x2t, *oB;
    cudaGetSymbolAddress((void**)&x1h, g_x1h);
    cudaGetSymbolAddress((void**)&x2t, g_x2t);
    cudaGetSymbolAddress((void**)&a0,  g_a0);
    cudaGetSymbolAddress((void**)&a1,  g_a1);
    cudaGetSymbolAddress((void**)&oB,  g_o);
    cudaGetSymbolAddress((void**)&wb0, g_wb0);
    cudaGetSymbolAddress((void**)&wb1, g_wb1);
    cudaGetSymbolAddress((void**)&wb2, g_wb2);
    cudaGetSymbolAddress((void**)&wb3, g_wb3);

    // SMEM: A halo (4x66 rows) + B triple buffer, pitch ICA+8
    const int SMEM0 = 4 * 66 * (16 + 8) * 2  + 3 * 64 * (16 + 8) * 2;    //  21,888
    const int SMEM1 = 4 * 66 * (128 + 8) * 2 + 3 * 64 * (128 + 8) * 2;   // 124,032
    cudaFuncSetAttribute(conv_mma_kernel<16>,  cudaFuncAttributeMaxDynamicSharedMemorySize, SMEM0);
    cudaFuncSetAttribute(conv_mma_kernel<128>, cudaFuncAttributeMaxDynamicSharedMemorySize, SMEM1);

    // 1) split / passthrough
    {
        int n = Bn * 32 * Hh * Ww;
        prep_kernel<<<(n + 255) / 256, 256>>>(x, out);
    }
    // 2) weight tiling (all four tensors, one launch)
    {
        int n = WN0 + 2 * WN1 + WN3;
        wprep_all<<<(n + 255) / 256, 256>>>(w0, w1, w2, w3, wb0, wb1, wb2, wb3);
    }
    // 3) convs, pure fp16, 128px x 64oc CTAs (R10 tiling, 2 CTAs/SM)
    conv_mma_kernel<16><<<dim3(NPIX / 128, 2), 256, SMEM0>>>(
        x1h, wb0, b0, a0, nullptr, HIDc);
    conv_mma_kernel<128><<<dim3(NPIX / 128, 2), 256, SMEM1>>>(
        a0, wb1, b1, a1, nullptr, HIDc);
    conv_mma_kernel<128><<<dim3(NPIX / 128, 2), 256, SMEM1>>>(
        a1, wb2, b2, a0, nullptr, HIDc);
    conv_mma_kernel<128><<<dim3(NPIX / 128, 5), 256, SMEM1>>>(
        a0, wb3, b3, nullptr, oB, OC4);
    // 4) expm (12-term matvec Taylor) + assembly + log_det
    expm_kernel<<<NPIX / 16, 256>>>(oB, scale, shift_p, rescale, reshift, out);

    (void)in_sizes; (void)n_in; (void)out_size;
}

// round 13
// speedup vs baseline: 1.3904x; 1.3904x over previous
#include <cuda_runtime.h>
#include <cuda_fp16.h>
#include <math.h>
#include <stdint.h>

// Shapes (fixed)
#define Bn   16
#define Hh   64
#define Ww   64
#define C1   16
#define C2   16
#define HIDc 128
#define OC4  272          // C2*(C2+1)
#define NPIX (Bn*Hh*Ww)   // 65536

// ---------------------------------------------------------------------------
__device__ __forceinline__ uint32_t smem_u32(const void* p) {
    uint32_t a;
    asm("{ .reg .u64 t; cvta.to.shared.u64 t, %1; cvt.u32.u64 %0, t; }" : "=r"(a) : "l"(p));
    return a;
}

__device__ __forceinline__ void ldsm_x4(uint32_t (&r)[4], uint32_t addr) {
    asm volatile("ldmatrix.sync.aligned.m8n8.x4.shared.b16 {%0,%1,%2,%3}, [%4];"
        : "=r"(r[0]), "=r"(r[1]), "=r"(r[2]), "=r"(r[3]) : "r"(addr));
}

__device__ __forceinline__ void mma16816(float (&d)[4], const uint32_t (&a)[4],
                                         uint32_t b0, uint32_t b1) {
    asm volatile("mma.sync.aligned.m16n8k16.row.col.f32.f16.f16.f32 "
        "{%0,%1,%2,%3}, {%4,%5,%6,%7}, {%8,%9}, {%0,%1,%2,%3};"
        : "+f"(d[0]), "+f"(d[1]), "+f"(d[2]), "+f"(d[3])
        : "r"(a[0]), "r"(a[1]), "r"(a[2]), "r"(a[3]), "r"(b0), "r"(b1));
}

__device__ __forceinline__ void cp16(uint32_t dst, const void* src, bool pred) {
    asm volatile("cp.async.cg.shared.global [%0], [%1], 16, %2;"
        :: "r"(dst), "l"(src), "r"(pred ? 16u : 0u) : "memory");
}
#define CP_COMMIT() asm volatile("cp.async.commit_group;" ::: "memory")
#define CP_WAIT0()  asm volatile("cp.async.wait_group 0;" ::: "memory")

__device__ __forceinline__ float eluf(float t) { return t > 0.0f ? t : expm1f(t); }

__device__ __forceinline__ float tanh_fast(float x) {
    float y;
    asm("tanh.approx.f32 %0, %1;" : "=f"(y) : "f"(x));
    return y;
}

// ---------------- scratch (device globals) ----------------
__device__ __align__(16) __half g_x1h[NPIX * C1];
__device__ __align__(16) float  g_x2t[NPIX * C2];
__device__ __align__(16) __half g_a0[NPIX * HIDc];
__device__ __align__(16) __half g_a1[NPIX * HIDc];
__device__ __align__(16) float  g_o [(size_t)NPIX * OC4];
// pre-swizzled weights in MMA B-fragment order:
// block = ((tt*KC + kc)*2 + wn)*2 + p ; 256 halves per block (lane*8 + q*4 + r*2 + h)
__device__ __align__(16) __half g_wb0[2 * 9 * 64 * 16];
__device__ __align__(16) __half g_wb1[2 * 9 * 64 * 128];
__device__ __align__(16) __half g_wb2[2 * 9 * 64 * 128];
__device__ __align__(16) __half g_wb3[5 * 9 * 64 * 128];

// ---------------------------------------------------------------------------
// prep: NCHW -> NHWC split (x1 as fp16, x2 fp32), passthrough, zero logdet
// ---------------------------------------------------------------------------
__global__ void prep_kernel(const float* __restrict__ x, float* __restrict__ out)
{
    int idx = blockIdx.x * blockDim.x + threadIdx.x;
    if (idx < Bn) out[(size_t)Bn * 32 * Hh * Ww + idx] = 0.0f;
    if (idx >= Bn * 32 * Hh * Ww) return;
    int b = idx >> 17;
    int c = (idx >> 12) & 31;
    int p = idx & 4095;
    float v = x[idx];
    int pix = (b << 12) + p;
    if (c < C1) {
        out[idx] = v;
        g_x1h[pix * C1 + c] = __float2half_rn(v);
    } else {
        g_x2t[pix * C2 + (c - C1)] = v;
    }
}

// ---------------------------------------------------------------------------
// wprep_all: tile all four weight tensors into fp16 MMA-B-fragment layout.
// For half index: block = idx/256, w = idx%256: l=w/8, q=(w%8)/4, r=(w%4)/2, h=w%2
// block: p = blk%2, wn = (blk/2)%2, kc = (blk/4)%KC, tt = blk/(4*KC)
// oc = (tt/9)*64 + wn*32 + (p*2+q)*8 + l/4 ; k = kc*16 + 2*(l%4) + r*8 + h
// ---------------------------------------------------------------------------
#define WN0 (2 * 9 * 64 * 16)
#define WN1 (2 * 9 * 64 * 128)
#define WN3 (5 * 9 * 64 * 128)
__global__ void wprep_all(const float* __restrict__ w0, const float* __restrict__ w1,
                          const float* __restrict__ w2, const float* __restrict__ w3,
                          __half* __restrict__ d0, __half* __restrict__ d1,
                          __half* __restrict__ d2, __half* __restrict__ d3)
{
    int gi = blockIdx.x * blockDim.x + threadIdx.x;
    const float* w; __half* d; int OC, ICA, li;
    if (gi < WN0)                 { li = gi;                 w = w0; d = d0; OC = HIDc; ICA = C1;   }
    else if (gi < WN0 + WN1)      { li = gi - WN0;           w = w1; d = d1; OC = HIDc; ICA = HIDc; }
    else if (gi < WN0 + 2 * WN1)  { li = gi - WN0 - WN1;     w = w2; d = d2; OC = HIDc; ICA = HIDc; }
    else if (gi < WN0 + 2 * WN1 + WN3) { li = gi - WN0 - 2 * WN1; w = w3; d = d3; OC = OC4; ICA = HIDc; }
    else return;
    const int KC = ICA / 16;
    int wrd = li & 255;
    int blk = li >> 8;
    int l = wrd >> 3;
    int q = (wrd >> 2) & 1;
    int r = (wrd >> 1) & 1;
    int h = wrd & 1;
    int p  = blk & 1;
    int wn = (blk >> 1) & 1;
    int kc = (blk >> 2) % KC;
    int tt = blk / (4 * KC);
    int tap  = tt % 9;
    int tile = tt / 9;
    int oc = tile * 64 + wn * 32 + (p * 2 + q) * 8 + (l >> 2);
    int k  = kc * 16 + 2 * (l & 3) + r * 8 + h;
    float v = (oc < OC) ? w[((size_t)oc * ICA + k) * 9 + tap] : 0.0f;
    d[li] = __float2half_rn(v);
}

// ---------------------------------------------------------------------------
// Implicit 3x3 conv via mma.sync (pure fp16); A halo resident in SMEM,
// B loaded per-kc straight from global (L2-hot, pre-swizzled fragments).
// CTA = 128 px (2 image rows) x 64 oc, 8 warps (4M x 2N), warp = 32px x 32oc.
// NO per-tap barriers; only one barrier after the A prologue.
// ---------------------------------------------------------------------------
template<int ICA>
__global__ __launch_bounds__(256)
void conv_mma_kernel(const __half* __restrict__ in,
                     const __half* __restrict__ wb,
                     const float* __restrict__ bias,
                     __half* __restrict__ out_h,
                     float* __restrict__ out_f32,
                     int OC_total)
{
    constexpr int PITCH = ICA + 8;
    constexpr int PB    = PITCH * 2;
    constexpr int AROWS = 4 * 66;
    constexpr int VPA   = ICA / 8;
    constexpr int KC    = ICA / 16;

    extern __shared__ char smem[];
    const uint32_t sA = smem_u32(smem);

    const int tid  = threadIdx.x;
    const int lane = tid & 31;
    const int warp = tid >> 5;
    const int warpN = warp & 1;
    const int warpM = warp >> 1;

    const int pixbase = blockIdx.x * 128;
    const int b  = pixbase >> 12;
    const int y0 = (pixbase & 4095) >> 6;
    const int ocb = blockIdx.y;
    const bool active = (ocb * 64 + warpN * 32) < OC_total;

    float acc[2][4][4];
    #pragma unroll
    for (int mt = 0; mt < 2; mt++)
        #pragma unroll
        for (int nt = 0; nt < 4; nt++)
            #pragma unroll
            for (int q = 0; q < 4; q++) acc[mt][nt][q] = 0.0f;

    // ---- prologue: A halo via cp.async (once) ----
    for (int vi = tid; vi < AROWS * VPA; vi += 256) {
        int row = vi / VPA;
        int kv  = vi % VPA;
        int yy  = y0 + row / 66 - 1;
        int xx  = (row % 66) - 1;
        bool ok = (yy >= 0 && yy < Hh && xx >= 0 && xx < Ww);
        size_t src = ok ? (((size_t)((b << 12) + (yy << 6) + xx)) * ICA + kv * 8) : 0;
        cp16(sA + row * PB + kv * 16, in + src, ok);
    }
    CP_COMMIT();
    CP_WAIT0();
    __syncthreads();

    if (active) {
        // per-lane A ldmatrix base offset
        const uint32_t a_base = (uint32_t)(((warpM >> 1) + 1) * 66
                              + (warpM & 1) * 32 + (lane & 15) + 1) * PB
                              + (uint32_t)(lane & 16);
        // B fragment pointer: blocks of 512B; per (tt,kc): 4 blocks (wn,p)
        // addr = wb + ((tt*KC + kc)*4 + wn*2 + p)*256 + lane*8   (halves)
        const __half* wwarp = wb + ((size_t)(ocb * 9) * KC * 4 + warpN * 2) * 256
                            + lane * 8;

        #pragma unroll (ICA == 16 ? 9 : 1)
        for (int tap = 0; tap < 9; tap++) {
            const int dy = tap / 3 - 1, dx = tap % 3 - 1;
            const uint32_t tapoff = (uint32_t)((dy * 66 + dx) * PB);
            const __half* wtap = wwarp + (size_t)tap * KC * 1024;
            #pragma unroll
            for (int kc = 0; kc < KC; kc++) {
                const uint32_t k0b = kc * 32;
                uint32_t A[2][4];
                #pragma unroll
                for (int mt = 0; mt < 2; mt++)
                    ldsm_x4(A[mt], sA + a_base + tapoff + k0b + (uint32_t)(mt * 16) * PB);
                const uint4 u0 = *(const uint4*)(wtap + kc * 1024);        // nt 0,1
                const uint4 u1 = *(const uint4*)(wtap + kc * 1024 + 256);  // nt 2,3
                #pragma unroll
                for (int mt = 0; mt < 2; mt++) {
                    mma16816(acc[mt][0], A[mt], u0.x, u0.y);
                    mma16816(acc[mt][1], A[mt], u0.z, u0.w);
                    mma16816(acc[mt][2], A[mt], u1.x, u1.y);
                    mma16816(acc[mt][3], A[mt], u1.z, u1.w);
                }
            }
        }
    }

    // --- epilogue ---
    if (!active) return;
    #pragma unroll
    for (int mt = 0; mt < 2; mt++) {
        #pragma unroll
        for (int nt = 0; nt < 4; nt++) {
            const int cl = warpN * 32 + nt * 8 + (lane & 3) * 2;
            const int oc = ocb * 64 + cl;
            if (oc >= OC_total) continue;
            const float b0 = bias[oc], b1 = bias[oc + 1];
            const int r0 = pixbase + (warpM >> 1) * 64 + (warpM & 1) * 32
                         + mt * 16 + (lane >> 2);
            #pragma unroll
            for (int h = 0; h < 2; h++) {
                const int pix = r0 + h * 8;
                float v0 = acc[mt][nt][2 * h]     + b0;
                float v1 = acc[mt][nt][2 * h + 1] + b1;
                if (out_f32) {
                    *(float2*)(out_f32 + (size_t)pix * OC4 + oc) = make_float2(v0, v1);
                } else {
                    v0 = eluf(v0);
                    v1 = eluf(v1);
                    __half h0 = __float2half_rn(v0);
                    __half h1 = __float2half_rn(v1);
                    uint32_t hw = (uint32_t)__half_as_ushort(h0) | ((uint32_t)__half_as_ushort(h1) << 16);
                    *(uint32_t*)(out_h + (size_t)pix * 128 + oc) = hw;
                }
            }
        }
    }
}

// ---------------------------------------------------------------------------
// expm kernel: y2 = sum_{k=0..12} A^k x2 / k!  (terms 13-18 < 2e-10, ||A||<=1)
// A via tanh.approx; trace via accurate tanhf. One syncwarp/iter (double buf).
// ---------------------------------------------------------------------------
__global__ __launch_bounds__(256)
void expm_kernel(const float* __restrict__ o,
                 const float* __restrict__ scale, const float* __restrict__ shift_p,
                 const float* __restrict__ rescale, const float* __restrict__ reshift,
                 float* __restrict__ out)
{
    __shared__ float sT[16][2][20];
    __shared__ float sY[16][17];
    __shared__ float sTr[8];

    const int tid  = threadIdx.x;
    const int lane = tid & 31;
    const int warp = tid >> 5;
    const int half = lane >> 4;
    const int r    = lane & 15;
    const int pixB = warp * 2 + half;

    const int pix_base = blockIdx.x * 16;
    const int b  = pix_base >> 12;
    const int p  = pix_base & 4095;
    const int y  = p >> 6;
    const int x0 = p & 63;
    const int pix = pix_base + pixB;

    const float sc = scale[0], sp = shift_p[0], rs = rescale[0], rf = reshift[0];
    const float* op = o + (size_t)pix * OC4;

    float arow[16];
    #pragma unroll
    for (int j = 0; j < 16; j++) {
        float v = op[(j + 1) * 16 + r];
        arow[j] = rs * tanh_fast(sc * v + sp) + rf;
    }
    // accurate trace (same math path as validated rounds)
    float tr = rs * tanhf(sc * op[(r + 1) * 16 + r] + sp) + rf;

    const float x2v = g_x2t[(size_t)pix * 16 + r];
    sT[pixB][0][r] = x2v;
    float yacc = x2v;
    __syncwarp();

    #pragma unroll
    for (int k = 1; k <= 12; k++) {
        const int prev = (k - 1) & 1, cur = k & 1;
        float s = 0.0f;
        #pragma unroll
        for (int j = 0; j < 16; j++) s = fmaf(arow[j], sT[pixB][prev][j], s);
        s *= (1.0f / (float)k);
        sT[pixB][cur][r] = s;
        yacc += s;
        __syncwarp();
    }

    sY[pixB][r] = yacc + op[r];

    #pragma unroll
    for (int off = 16; off > 0; off >>= 1) tr += __shfl_down_sync(0xffffffffu, tr, off);
    if (lane == 0) sTr[warp] = tr;
    __syncthreads();
    if (tid == 0) {
        float s = 0.0f;
        #pragma unroll
        for (int w2 = 0; w2 < 8; w2++) s += sTr[w2];
        atomicAdd(out + (size_t)Bn * 32 * Hh * Ww + b, s);
    }

    const int c  = tid >> 4;
    const int p2 = tid & 15;
    out[((size_t)(b * 32 + 16 + c)) * (Hh * Ww) + y * Ww + x0 + p2] = sY[p2][c];
}

// ---------------------------------------------------------------------------
extern "C" void kernel_launch(void* const* d_in, const int* in_sizes, int n_in,
                              void* d_out, int out_size)
{
    const float* x       = (const float*)d_in[0];
    const float* scale   = (const float*)d_in[1];
    const float* shift_p = (const float*)d_in[2];
    const float* rescale = (const float*)d_in[3];
    const float* reshift = (const float*)d_in[4];
    const float* w0 = (const float*)d_in[5];
    const float* b0 = (const float*)d_in[6];
    const float* w1 = (const float*)d_in[7];
    const float* b1 = (const float*)d_in[8];
    const float* w2 = (const float*)d_in[9];
    const float* b2 = (const float*)d_in[10];
    const float* w3 = (const float*)d_in[11];
    const float* b3 = (const float*)d_in[12];
    float* out = (float*)d_out;

    __half *x1h, *a0, *a1, *wb0, *wb1, *wb2, *wb3;
    float *x2t, *oB;
    cudaGetSymbolAddress((void**)&x1h, g_x1h);
    cudaGetSymbolAddress((void**)&x2t, g_x2t);
    cudaGetSymbolAddress((void**)&a0,  g_a0);
    cudaGetSymbolAddress((void**)&a1,  g_a1);
    cudaGetSymbolAddress((void**)&oB,  g_o);
    cudaGetSymbolAddress((void**)&wb0, g_wb0);
    cudaGetSymbolAddress((void**)&wb1, g_wb1);
    cudaGetSymbolAddress((void**)&wb2, g_wb2);
    cudaGetSymbolAddress((void**)&wb3, g_wb3);

    // SMEM: A halo only (4x66 rows), pitch ICA+8
    const int SMEM0 = 4 * 66 * (16 + 8) * 2;     //  12,672
    const int SMEM1 = 4 * 66 * (128 + 8) * 2;    //  71,808 -> 3 CTAs/SM
    cudaFuncSetAttribute(conv_mma_kernel<16>,  cudaFuncAttributeMaxDynamicSharedMemorySize, SMEM0);
    cudaFuncSetAttribute(conv_mma_kernel<128>, cudaFuncAttributeMaxDynamicSharedMemorySize, SMEM1);

    // 1) split / passthrough
    {
        int n = Bn * 32 * Hh * Ww;
        prep_kernel<<<(n + 255) / 256, 256>>>(x, out);
    }
    // 2) weight tiling into fragment layout (all four tensors, one launch)
    {
        int n = WN0 + 2 * WN1 + WN3;
        wprep_all<<<(n + 255) / 256, 256>>>(w0, w1, w2, w3, wb0, wb1, wb2, wb3);
    }
    // 3) convs, pure fp16, B direct-from-global fragments, barrier-free mainloop
    conv_mma_kernel<16><<<dim3(NPIX / 128, 2), 256, SMEM0>>>(
        x1h, wb0, b0, a0, nullptr, HIDc);
    conv_mma_kernel<128><<<dim3(NPIX / 128, 2), 256, SMEM1>>>(
        a0, wb1, b1, a1, nullptr, HIDc);
    conv_mma_kernel<128><<<dim3(NPIX / 128, 2), 256, SMEM1>>>(
        a1, wb2, b2, a0, nullptr, HIDc);
    conv_mma_kernel<128><<<dim3(NPIX / 128, 5), 256, SMEM1>>>(
        a0, wb3, b3, nullptr, oB, OC4);
    // 4) expm (12-term matvec Taylor) + assembly + log_det
    expm_kernel<<<NPIX / 16, 256>>>(oB, scale, shift_p, rescale, reshift, out);

    (void)in_sizes; (void)n_in; (void)out_size;
}